// round 11
// baseline (speedup 1.0000x reference)
#include <cuda_runtime.h>
#include <cstdint>

// DSAttention tf32 flash attention, cp.async pipeline, + prep kernel that
// rna-rounds K/V into MMA-native scratch layouts:
//   g_Kp: [b*h][s][64]  columns interleaved (c, c+4) per 8-group  -> QK B-frag = 1 LDS.64
//   g_Vt: [b*h][e][2048] V transposed, s interleaved per 8-group  -> PV B-frag = 1 LDS.64
// B=2, L=S=2048, H=8, E=64. BM=BN=64, 4 warps, 128 thr/CTA, 3 CTAs/SM.

#define LQ 2048
#define HH 8
#define BM 64
#define BN 64
#define ED 64
#define NTHREADS 128
#define KSTR 72     // 72 % 32 == 8 -> 2-way (floor) conflicts for LDS.64 frags
#define VSTR 72
#define PSTR 68

#define SK_F   (64 * KSTR)        // 4608 per buffer
#define SV_F   (64 * VSTR)        // 4608
#define SQP_F  (BM * PSTR)        // 4352
#define SMEM_FLOATS (2 * SK_F + SV_F + SQP_F + 64)
#define SMEM_BYTES  (SMEM_FLOATS * 4)   // 72960 B -> 3 CTAs/SM

__device__ float g_Kp[2 * 8 * 2048 * 64];   // 8 MB scratch
__device__ float g_Vt[2 * 8 * 64 * 2048];   // 8 MB scratch

__device__ __forceinline__ float tf32r(float x) {
    uint32_t u;
    asm("cvt.rna.tf32.f32 %0, %1;" : "=r"(u) : "f"(x));
    return __uint_as_float(u);
}

__device__ __forceinline__ void cpasync16(uint32_t dst, const void* src) {
    asm volatile("cp.async.cg.shared.global [%0], [%1], 16;" :: "r"(dst), "l"(src));
}
__device__ __forceinline__ void cp_commit() {
    asm volatile("cp.async.commit_group;" ::: "memory");
}
__device__ __forceinline__ void cp_wait1() {
    asm volatile("cp.async.wait_group 1;" ::: "memory");
}
__device__ __forceinline__ void cp_wait0() {
    asm volatile("cp.async.wait_group 0;" ::: "memory");
}

__device__ __forceinline__ void mma_tf32(float* d, const uint32_t* a,
                                         uint32_t b0, uint32_t b1) {
    asm volatile(
        "mma.sync.aligned.m16n8k8.row.col.f32.tf32.tf32.f32 "
        "{%0,%1,%2,%3}, {%4,%5,%6,%7}, {%8,%9}, {%0,%1,%2,%3};"
        : "+f"(d[0]), "+f"(d[1]), "+f"(d[2]), "+f"(d[3])
        : "r"(a[0]), "r"(a[1]), "r"(a[2]), "r"(a[3]), "r"(b0), "r"(b1));
}

// ---------------- prep: rna-round K,V into scratch, permute/transpose ----------------
__global__ __launch_bounds__(256)
void prep_kernel(const float* __restrict__ Kg, const float* __restrict__ Vg)
{
    const int stile = blockIdx.x;      // 0..31 (64 s-rows)
    const int h     = blockIdx.y;
    const int b     = blockIdx.z;
    const int tid   = threadIdx.x;
    const int bh    = b * HH + h;
    const int s0    = stile * 64;

    __shared__ float tile[64][65];

    // ---- K: rna + (c, c+4) interleave per 8-group; layout [bh][s][64] ----
    const float* Kbh = Kg + ((size_t)(b * LQ) * HH + h) * ED;
    float* Kp = g_Kp + (size_t)bh * LQ * ED;
    #pragma unroll
    for (int it = 0; it < 2; ++it) {
        int u  = tid + it * 256;       // 0..511 = 64 rows x 8 groups
        int r  = u >> 3;
        int c8 = u & 7;
        const float* src = Kbh + (size_t)(s0 + r) * (HH * ED) + 8 * c8;
        float4 a  = *(const float4*)(src);
        float4 bb = *(const float4*)(src + 4);
        a.x = tf32r(a.x); a.y = tf32r(a.y); a.z = tf32r(a.z); a.w = tf32r(a.w);
        bb.x = tf32r(bb.x); bb.y = tf32r(bb.y); bb.z = tf32r(bb.z); bb.w = tf32r(bb.w);
        float* dst = Kp + (size_t)(s0 + r) * ED + 8 * c8;
        *(float4*)(dst)     = make_float4(a.x, bb.x, a.y, bb.y);
        *(float4*)(dst + 4) = make_float4(a.z, bb.z, a.w, bb.w);
    }

    // ---- V: rna + transpose to [bh][e][2048], s interleaved per 8-group ----
    const float* Vbh = Vg + ((size_t)(b * LQ) * HH + h) * ED;
    #pragma unroll
    for (int it = 0; it < 4; ++it) {
        int u  = tid + it * 256;       // 0..1023 = 64 rows x 16 chunks
        int r  = u >> 4;
        int c4 = u & 15;
        float4 v = *(const float4*)(Vbh + (size_t)(s0 + r) * (HH * ED) + 4 * c4);
        tile[r][4 * c4 + 0] = tf32r(v.x);
        tile[r][4 * c4 + 1] = tf32r(v.y);
        tile[r][4 * c4 + 2] = tf32r(v.z);
        tile[r][4 * c4 + 3] = tf32r(v.w);
    }
    __syncthreads();
    float* Vt = g_Vt + (size_t)bh * ED * LQ;
    #pragma unroll
    for (int it = 0; it < 4; ++it) {
        int u    = tid + it * 256;     // 0..1023 = 64 e-rows x 8 groups x 2 halves
        int e    = u >> 4;
        int c8   = (u >> 1) & 7;
        int half = u & 1;
        int sg   = 8 * c8;
        int p0   = 4 * half;
        // physical position p holds logical s = 4*(p&1) + (p>>1)  (within 8-group)
        float4 o;
        o.x = tile[sg + 4 * ((p0 + 0) & 1) + ((p0 + 0) >> 1)][e];
        o.y = tile[sg + 4 * ((p0 + 1) & 1) + ((p0 + 1) >> 1)][e];
        o.z = tile[sg + 4 * ((p0 + 2) & 1) + ((p0 + 2) >> 1)][e];
        o.w = tile[sg + 4 * ((p0 + 3) & 1) + ((p0 + 3) >> 1)][e];
        *(float4*)(Vt + (size_t)e * LQ + s0 + sg + p0) = o;
    }
}

// ---------------- main flash-attention kernel ----------------
__global__ __launch_bounds__(NTHREADS, 3)
void dsattn_tc(const float* __restrict__ Qg, const float* __restrict__ Taug,
               const float* __restrict__ Dg, float* __restrict__ Og)
{
    const float scale = 0.125f;

    const int mtile = (int)gridDim.x - 1 - (int)blockIdx.x;   // heavy first
    const int h     = blockIdx.y;
    const int b     = blockIdx.z;
    const int bh    = b * HH + h;

    const int tid  = threadIdx.x;
    const int wid  = tid >> 5;
    const int lane = tid & 31;
    const int g    = lane >> 2;
    const int t4   = lane & 3;

    extern __shared__ float smem[];
    float* sK0 = smem;
    float* sK1 = sK0 + SK_F;
    float* sVt = sK1 + SK_F;
    float* sQP = sVt + SV_F;
    float* sD  = sQP + SQP_F;

    const uint32_t smem_u32 = (uint32_t)__cvta_generic_to_shared(smem);
    const uint32_t sK0u = smem_u32;
    const uint32_t sK1u = sK0u + SK_F * 4;
    const uint32_t sVu  = sK1u + SK_F * 4;
    const uint32_t sQPu = sVu + SV_F * 4;
    const uint32_t sDu  = sQPu + SQP_F * 4;

    const float ts = Taug[b] * scale;
    const int wrow = wid * 16;

    const int r_lo = tid >> 4;     // + 8*it -> row
    const int c4   = tid & 15;
    const float* Qbase  = Qg + ((size_t)(b * LQ) * HH + h) * ED;
    const float* Kpbase = g_Kp + (size_t)bh * LQ * ED;
    const float* Vtbase = g_Vt + (size_t)bh * ED * LQ;
    const float* Dbase  = Dg + b * LQ;

    // ---- prologue: Q tile + K tile 0 ----
    {
        const int q0 = mtile * BM;
        #pragma unroll
        for (int it = 0; it < 8; ++it) {
            int r = r_lo + it * 8;
            cpasync16(sQPu + (r * PSTR + c4 * 4) * 4,
                      Qbase + (size_t)(q0 + r) * (HH * ED) + c4 * 4);
            cpasync16(sK0u + (r * KSTR + c4 * 4) * 4,
                      Kpbase + (size_t)r * ED + c4 * 4);
        }
        cp_commit();
        cp_wait0();
    }
    __syncthreads();

    // ---- Q fragments (rna-rounded once) ----
    uint32_t qa[8][4];
    {
        const float* qb = sQP + (wrow + g) * PSTR;
        #pragma unroll
        for (int k = 0; k < 8; ++k) {
            qa[k][0] = __float_as_uint(tf32r(qb[8 * k + t4]));
            qa[k][1] = __float_as_uint(tf32r(qb[8 * PSTR + 8 * k + t4]));
            qa[k][2] = __float_as_uint(tf32r(qb[8 * k + t4 + 4]));
            qa[k][3] = __float_as_uint(tf32r(qb[8 * PSTR + 8 * k + t4 + 4]));
        }
    }

    float m_i[2] = {-1e30f, -1e30f};
    float l_i[2] = {0.f, 0.f};
    float Oacc[8][4];
    #pragma unroll
    for (int j = 0; j < 8; ++j)
        #pragma unroll
        for (int i = 0; i < 4; ++i) Oacc[j][i] = 0.f;

    const int row0 = mtile * BM + wrow + g;
    const int row1 = row0 + 8;
    const int nkt  = mtile + 1;

    for (int kt = 0; kt < nkt; ++kt) {
        __syncthreads();

        const float* sK   = (kt & 1) ? sK1 : sK0;
        const uint32_t sKnu = (kt & 1) ? sK0u : sK1u;

        // group A: Vt(kt) + delta(kt)
        {
            const int kr0 = kt * BN;
            #pragma unroll
            for (int it = 0; it < 8; ++it) {
                int r = r_lo + it * 8;           // e-row
                cpasync16(sVu + (r * VSTR + c4 * 4) * 4,
                          Vtbase + (size_t)r * LQ + kr0 + c4 * 4);
            }
            if (tid < 16) cpasync16(sDu + tid * 16, Dbase + kr0 + tid * 4);
            cp_commit();
        }
        // group B: K(kt+1)
        if (kt + 1 < nkt) {
            const int kr0 = (kt + 1) * BN;
            #pragma unroll
            for (int it = 0; it < 8; ++it) {
                int r = r_lo + it * 8;
                cpasync16(sKnu + (r * KSTR + c4 * 4) * 4,
                          Kpbase + (size_t)(kr0 + r) * ED + c4 * 4);
            }
        }
        cp_commit();

        // ---- S = Q @ K^T ---- (interleaved K: one LDS.64 per B-frag)
        float Sacc[8][4];
        #pragma unroll
        for (int j = 0; j < 8; ++j)
            #pragma unroll
            for (int i = 0; i < 4; ++i) Sacc[j][i] = 0.f;

        #pragma unroll
        for (int k = 0; k < 8; ++k) {
            #pragma unroll
            for (int j = 0; j < 8; ++j) {
                float2 bb = *(const float2*)(sK + (8 * j + g) * KSTR + 8 * k + 2 * t4);
                mma_tf32(Sacc[j], qa[k],
                         __float_as_uint(bb.x), __float_as_uint(bb.y));
            }
        }

        cp_wait1();        // Vt + delta landed
        __syncthreads();

        // ---- scale + delta + causal mask ----
        const int cb = kt * BN + 2 * t4;
        #pragma unroll
        for (int j = 0; j < 8; ++j) {
            int c0 = cb + 8 * j;
            float2 d = *(const float2*)(sD + 8 * j + 2 * t4);
            float dx = d.x * scale, dy = d.y * scale;
            float s0 = Sacc[j][0] * ts + dx;
            float s1 = Sacc[j][1] * ts + dy;
            float s2 = Sacc[j][2] * ts + dx;
            float s3 = Sacc[j][3] * ts + dy;
            if (c0     > row0) s0 = -1e30f;
            if (c0 + 1 > row0) s1 = -1e30f;
            if (c0     > row1) s2 = -1e30f;
            if (c0 + 1 > row1) s3 = -1e30f;
            Sacc[j][0] = s0; Sacc[j][1] = s1; Sacc[j][2] = s2; Sacc[j][3] = s3;
        }

        // ---- online softmax ----
        #pragma unroll
        for (int hh = 0; hh < 2; ++hh) {
            float mx = -1e30f;
            #pragma unroll
            for (int j = 0; j < 8; ++j)
                mx = fmaxf(mx, fmaxf(Sacc[j][2 * hh], Sacc[j][2 * hh + 1]));
            mx = fmaxf(mx, __shfl_xor_sync(0xffffffffu, mx, 1));
            mx = fmaxf(mx, __shfl_xor_sync(0xffffffffu, mx, 2));
            float mnew  = fmaxf(m_i[hh], mx);
            float alpha = __expf(m_i[hh] - mnew);
            float psum = 0.f;
            const int prow = wrow + g + 8 * hh;
            #pragma unroll
            for (int j = 0; j < 8; ++j) {
                float p0 = __expf(Sacc[j][2 * hh]     - mnew);
                float p1 = __expf(Sacc[j][2 * hh + 1] - mnew);
                psum += p0 + p1;
                *(float2*)(sQP + prow * PSTR + 8 * j + 2 * t4) =
                    make_float2(tf32r(p0), tf32r(p1));
            }
            psum += __shfl_xor_sync(0xffffffffu, psum, 1);
            psum += __shfl_xor_sync(0xffffffffu, psum, 2);
            l_i[hh] = l_i[hh] * alpha + psum;
            m_i[hh] = mnew;
            #pragma unroll
            for (int j = 0; j < 8; ++j) {
                Oacc[j][2 * hh]     *= alpha;
                Oacc[j][2 * hh + 1] *= alpha;
            }
        }
        __syncwarp();   // P round-trip is warp-local

        // ---- O += P @ V ---- (transposed+interleaved V: one LDS.64 per B-frag)
        #pragma unroll
        for (int k = 0; k < 8; ++k) {
            const float* pr = sQP + (wrow + g) * PSTR + 8 * k;
            uint32_t pa[4];
            pa[0] = __float_as_uint(pr[t4]);
            pa[1] = __float_as_uint(pr[8 * PSTR + t4]);
            pa[2] = __float_as_uint(pr[t4 + 4]);
            pa[3] = __float_as_uint(pr[8 * PSTR + t4 + 4]);
            #pragma unroll
            for (int j = 0; j < 8; ++j) {
                float2 vv = *(const float2*)(sVt + (8 * j + g) * VSTR + 8 * k + 2 * t4);
                mma_tf32(Oacc[j], pa,
                         __float_as_uint(vv.x), __float_as_uint(vv.y));
            }
        }

        cp_wait0();    // K(kt+1) landed; visibility via top-of-loop barrier
    }

    // ---- finalize & write ----
    {
        float inv0 = 1.0f / l_i[0];
        float inv1 = 1.0f / l_i[1];
        float* o0 = Og + (((size_t)(b * LQ + row0)) * HH + h) * ED;
        float* o1 = Og + (((size_t)(b * LQ + row1)) * HH + h) * ED;
        #pragma unroll
        for (int j = 0; j < 8; ++j) {
            int e = 8 * j + 2 * t4;
            *(float2*)(o0 + e) = make_float2(Oacc[j][0] * inv0, Oacc[j][1] * inv0);
            *(float2*)(o1 + e) = make_float2(Oacc[j][2] * inv1, Oacc[j][3] * inv1);
        }
    }
}

extern "C" void kernel_launch(void* const* d_in, const int* in_sizes, int n_in,
                              void* d_out, int out_size)
{
    const float* Q     = (const float*)d_in[0];
    const float* K     = (const float*)d_in[1];
    const float* V     = (const float*)d_in[2];
    const float* tau   = (const float*)d_in[3];
    const float* delta = (const float*)d_in[4];
    float* out = (float*)d_out;

    cudaFuncSetAttribute(dsattn_tc,
                         cudaFuncAttributeMaxDynamicSharedMemorySize, SMEM_BYTES);

    dim3 pgrid(LQ / 64, HH, 2);
    prep_kernel<<<pgrid, 256>>>(K, V);

    dim3 grid(LQ / BM, HH, 2);   // (32, 8, 2)
    dsattn_tc<<<grid, NTHREADS, SMEM_BYTES>>>(Q, tau, delta, out);
}